// round 8
// baseline (speedup 1.0000x reference)
#include <cuda_runtime.h>
#include <cstdint>

// Problem constants
#define B        64
#define N_SV     63
#define HID      512
#define NEW_W    28
#define NEW_H    28
#define NCELL    (NEW_W * NEW_H)     // 784
#define HT       8                   // h-channels per block
#define NTHREADS 256
#define TILE_F   (HT * NCELL)        // 6272 floats per block tile
#define TILE_F8  (TILE_F / 8)        // 784 chunks of 32B per tile
#define NPAIR    (N_SV * HT)         // 504
#define OCCW     25                  // ceil(784/32) occupancy words

// 256-bit store with L2 evict_last (required .v8.b32 form on sm_103a).
__device__ __forceinline__ void st256_el(void* p,
                                         int r0, int r1, int r2, int r3,
                                         int r4, int r5, int r6, int r7) {
    asm volatile(
        "st.global.L2::evict_last.v8.b32 [%0], {%1,%2,%3,%4,%5,%6,%7,%8};"
        :: "l"(p), "r"(r0), "r"(r1), "r"(r2), "r"(r3),
           "r"(r4), "r"(r5), "r"(r6), "r"(r7) : "memory");
}

// ---------------------------------------------------------------------------
// Single fused kernel, zero global atomics. Each block owns output tile
// (b, h0..h0+8, 784 cells) exclusively.
//   Stage A: agents compute cells; valid agents zero their smem row
//            (sGridT[cell][0..7]) and set the cell's occupancy bit.
//   Stage B: 504 hoisted enc loads -> smem atomicMax into occupied rows
//            (values <= 0 skipped: they lose to the 0 init; survivors >= 0
//            so int-compare on float bits is exact).
//   Stage C: store loop. Each 32B chunk = 8 cells of one channel row.
//            Occupancy byte == 0 (>=92% of chunks) -> store zeros directly;
//            else assemble from smem. Pure STG.256, no RMW on global.
// ---------------------------------------------------------------------------
__global__ __launch_bounds__(NTHREADS)
void fused_raster_kernel(const float* __restrict__ pos,     // (B, N_SV, 3)
                         const float* __restrict__ enc,     // (B, N_SV, HID)
                         const int*   __restrict__ lengths, // (B,)
                         float* __restrict__ out)           // (B, HID, 28, 28)
{
    const int b   = blockIdx.x;
    const int h0  = blockIdx.y * HT;
    const int tid = threadIdx.x;

    __shared__ float    sGridT[NCELL * HT];  // [cell][hh], 25088 B (sparse-init)
    __shared__ int      sCell[N_SV];         // cell per agent, -1 invalid
    __shared__ unsigned occ[OCCW];           // per-cell occupancy bits

    // --- Hoisted enc loads (independent of everything below) ---
    const float* encB = enc + (size_t)b * N_SV * HID + h0;
    const int i0 = tid, i1 = tid + NTHREADS;
    const bool p0 = (i0 < NPAIR), p1 = (i1 < NPAIR);
    float v0 = 0.f, v1 = 0.f;
    if (p0) v0 = __ldcs(encB + (i0 >> 3) * HID + (i0 & 7));
    if (p1) v1 = __ldcs(encB + (i1 >> 3) * HID + (i1 & 7));

    // --- Stage A ---
    if (tid < OCCW) occ[tid] = 0u;
    if (tid < N_SV) {
        int cell = -1;
        if (tid < lengths[b]) {
            const float x = pos[(b * N_SV + tid) * 3 + 0];
            const float y = pos[(b * N_SV + tid) * 3 + 1];
            int xI = (int)((x * (float)NEW_W) / 224.0f);   // trunc toward 0
            int yI = (int)((y * (float)NEW_H) / 224.0f);
            if (xI < NEW_W && yI < NEW_H) {
                if (xI < 0) xI = 0;
                if (yI < 0) yI = 0;
                cell = xI * NEW_H + yI;
            }
        }
        sCell[tid] = cell;
        if (cell >= 0) {
            // zero this cell's 8-float row (duplicates on collision are fine)
            float4* row = (float4*)&sGridT[cell * HT];
            row[0] = make_float4(0.f, 0.f, 0.f, 0.f);
            row[1] = make_float4(0.f, 0.f, 0.f, 0.f);
        }
    }
    __syncthreads();

    // --- Stage B: set occupancy bits + smem scatter-max ---
    if (tid < N_SV) {
        const int cell = sCell[tid];
        if (cell >= 0) atomicOr(&occ[cell >> 5], 1u << (cell & 31));
    }
    if (p0 && v0 > 0.f) {
        const int c = sCell[i0 >> 3];
        if (c >= 0) atomicMax((int*)&sGridT[c * HT + (i0 & 7)], __float_as_int(v0));
    }
    if (p1 && v1 > 0.f) {
        const int c = sCell[i1 >> 3];
        if (c >= 0) atomicMax((int*)&sGridT[c * HT + (i1 & 7)], __float_as_int(v1));
    }
    __syncthreads();

    // --- Stage C: pure-store sweep of the tile ---
    char* outC = (char*)(out + ((size_t)b * HID + h0) * NCELL);
    #pragma unroll
    for (int k = 0; k < 4; k++) {                 // 3 full strides + remainder
        const int j = tid + k * NTHREADS;         // chunk id, [0, 784)
        if (j >= TILE_F8) break;
        const int hh = j / (NCELL / 8);           // j / 98
        const int c0 = (j - hh * (NCELL / 8)) * 8;
        void* dst = outC + ((size_t)hh * NCELL + c0) * 4;

        const unsigned byte = (occ[c0 >> 5] >> (c0 & 31)) & 0xFFu;
        if (byte == 0u) {
            st256_el(dst, 0, 0, 0, 0, 0, 0, 0, 0);
        } else {
            int f[8];
            #pragma unroll
            for (int bb = 0; bb < 8; bb++)
                f[bb] = (byte >> bb) & 1u
                      ? __float_as_int(sGridT[(c0 + bb) * HT + hh]) : 0;
            st256_el(dst, f[0], f[1], f[2], f[3], f[4], f[5], f[6], f[7]);
        }
    }
}

extern "C" void kernel_launch(void* const* d_in, const int* in_sizes, int n_in,
                              void* d_out, int out_size) {
    const float* pos     = (const float*)d_in[0];   // (B, N_SV, 3)
    const float* enc     = (const float*)d_in[1];   // (B, N_SV, HID)
    const int*   lengths = (const int*)d_in[2];     // (B,)

    dim3 grid(B, HID / HT);            // (64, 64) = 4096 blocks
    fused_raster_kernel<<<grid, NTHREADS>>>(pos, enc, lengths, (float*)d_out);
}

// round 9
// speedup vs baseline: 1.0986x; 1.0986x over previous
#include <cuda_runtime.h>
#include <cstdint>

// Problem constants
#define B        64
#define N_SV     63
#define HID      512
#define NEW_W    28
#define NEW_H    28
#define NCELL    (NEW_W * NEW_H)     // 784
#define HT       16                  // h-channels per block
#define NTHREADS 256
#define TILE_F   (HT * NCELL)        // 12544 floats per block tile
#define TILE_F8  (TILE_F / 8)        // 1568 x 32B chunks per tile
#define NPAIR    (N_SV * HT)         // 1008 (agent, channel) pairs per block

// 256-bit zero store with L2 evict_last (sm_103a requires the .v8.b32 form).
// Output (102.8 MB) fits in the 126 MB L2: keeping its lines resident-dirty
// across graph replays avoids most DRAM writeback (R7-validated win).
__device__ __forceinline__ void st_zero256_evict_last(void* p) {
    asm volatile(
        "st.global.L2::evict_last.v8.b32 [%0], {%1,%1,%1,%1,%1,%1,%1,%1};"
        :: "l"(p), "r"(0) : "memory");
}

// ---------------------------------------------------------------------------
// Single fused kernel (R7 structure, HT=16). Each block exclusively owns
// output tile (b, h0..h0+16, all 784 cells).
//   Prologue: agent cells (63 threads) + this thread's <=4 enc values are
//             loaded FIRST so global-load latency overlaps the fill.
//   Phase A : 6.125 strides of 256-bit zero stores straight to global.
//   barrier : orders zeros before patches within the block.
//   Phase B : <=4 no-return atomicMax (REDG.MAX) per thread patch the
//             occupied cells. Values <= 0 skipped (lose to the 0 init);
//             survivors >= 0 so int-compare on float bits is exact.
// ---------------------------------------------------------------------------
__global__ __launch_bounds__(NTHREADS)
void fused_raster_kernel(const float* __restrict__ pos,     // (B, N_SV, 3)
                         const float* __restrict__ enc,     // (B, N_SV, HID)
                         const int*   __restrict__ lengths, // (B,)
                         float* __restrict__ out)           // (B, HID, 28, 28)
{
    const int b   = blockIdx.x;
    const int h0  = blockIdx.y * HT;
    const int tid = threadIdx.x;

    __shared__ int sCell[N_SV];   // cell index per agent, -1 if invalid

    // --- Prologue 1: agent validity + cell index (first 63 threads) ---
    if (tid < N_SV) {
        int cell = -1;
        if (tid < lengths[b]) {
            const float x = pos[(b * N_SV + tid) * 3 + 0];
            const float y = pos[(b * N_SV + tid) * 3 + 1];
            // Reference math: int(x * 28 / 224), trunc toward zero
            int xI = (int)((x * (float)NEW_W) / 224.0f);
            int yI = (int)((y * (float)NEW_H) / 224.0f);
            if (xI < NEW_W && yI < NEW_H) {
                if (xI < 0) xI = 0;
                if (yI < 0) yI = 0;
                cell = xI * NEW_H + yI;
            }
        }
        sCell[tid] = cell;
    }

    // --- Prologue 2: hoist this thread's enc loads (independent of fill) ---
    // pairs i = tid + k*256, k = 0..3 (1008 total; k=3 valid for tid<240)
    const float* encB = enc + (size_t)b * N_SV * HID + h0;
    float v[4];
    bool  pv[4];
    #pragma unroll
    for (int k = 0; k < 4; k++) {
        const int i = tid + k * NTHREADS;
        pv[k] = (i < NPAIR);
        v[k]  = 0.f;
        if (pv[k]) v[k] = __ldcs(encB + (i >> 4) * HID + (i & (HT - 1)));
    }

    // --- Phase A: zero the tile directly in global (256-bit, evict_last) ---
    // Tile base is 32B-aligned: (b*HID+h0)*NCELL*4 is a multiple of 3136.
    float* outB = out + ((size_t)b * HID + h0) * NCELL;
    char* outC = (char*)outB;
    // 1568 chunks / 256 threads = 6 full strides + 32-thread remainder
    #pragma unroll
    for (int k = 0; k < TILE_F8 / NTHREADS; k++)               // 6 iterations
        st_zero256_evict_last(outC + (size_t)(tid + k * NTHREADS) * 32);
    if (tid < TILE_F8 - (TILE_F8 / NTHREADS) * NTHREADS)       // last 32
        st_zero256_evict_last(outC + (size_t)(tid + (TILE_F8 / NTHREADS) * NTHREADS) * 32);

    // Order: sCell writes visible + zeros complete before patches.
    __syncthreads();

    // --- Phase B: patch occupied cells with no-return global atomicMax ---
    int* outBi = (int*)outB;
    #pragma unroll
    for (int k = 0; k < 4; k++) {
        if (pv[k] && v[k] > 0.f) {
            const int i = tid + k * NTHREADS;
            const int c = sCell[i >> 4];
            if (c >= 0)
                atomicMax(outBi + (i & (HT - 1)) * NCELL + c, __float_as_int(v[k]));
        }
    }
}

extern "C" void kernel_launch(void* const* d_in, const int* in_sizes, int n_in,
                              void* d_out, int out_size) {
    const float* pos     = (const float*)d_in[0];   // (B, N_SV, 3)
    const float* enc     = (const float*)d_in[1];   // (B, N_SV, HID)
    const int*   lengths = (const int*)d_in[2];     // (B,)

    dim3 grid(B, HID / HT);            // (64, 32) = 2048 blocks
    fused_raster_kernel<<<grid, NTHREADS>>>(pos, enc, lengths, (float*)d_out);
}